// round 9
// baseline (speedup 1.0000x reference)
#include <cuda_runtime.h>

#define DX 256
#define DY 256
#define DZ 32
#define VOL (DX * DY * DZ)   // 2,097,152

// Precomputed int16 weights, interleaved [dir][voxel][8] (16B/voxel) = 96 MB,
// plus 8 MB ping-pong scratch. Device globals = the allowed scratch mechanism.
__device__ uint4 g_weights[3][VOL];
__device__ float g_scratch[VOL];

// Neighbor shift tables (row, col) from the reference ZeroPad2d set.
// DIR=0: row->x, col->y (channels 0..7);  DIR=1: row->x, col->z (8..15);
// DIR=2: row->y, col->z (16..23).
__device__ __constant__ const int c_dr[8] = { 1, 1, 1, 0, 0, -1, -1, -1 };
__device__ __constant__ const int c_dc[8] = { 1, 0, -1, 1, -1, 1, 0, -1 };

// Single-use guidance: stream through, evict first.
__device__ __forceinline__ float ldcs(const float* p) {
    float v;
    asm volatile("ld.global.cs.f32 %0, [%1];" : "=f"(v) : "l"(p));
    return v;
}
// 256-bit accesses with L2 evict-last (the only width ptxas allows it on).
__device__ __forceinline__ void ldg256_sticky(const uint4* p, uint4& a, uint4& b) {
    asm volatile("ld.global.L2::evict_last.v8.b32 {%0,%1,%2,%3,%4,%5,%6,%7}, [%8];"
                 : "=r"(a.x), "=r"(a.y), "=r"(a.z), "=r"(a.w),
                   "=r"(b.x), "=r"(b.y), "=r"(b.z), "=r"(b.w)
                 : "l"(p));
}
__device__ __forceinline__ void stg256_sticky(uint4* p, uint4 a, uint4 b) {
    asm volatile("st.global.L2::evict_last.v8.b32 [%0], {%1,%2,%3,%4,%5,%6,%7,%8};"
                 :: "l"(p),
                    "r"(a.x), "r"(a.y), "r"(a.z), "r"(a.w),
                    "r"(b.x), "r"(b.y), "r"(b.z), "r"(b.w)
                 : "memory");
}

__device__ __forceinline__ void decode8(const uint4 w, float* wf) {
    wf[0] = (float)(short)(w.x & 0xffff); wf[1] = (float)(short)(w.x >> 16);
    wf[2] = (float)(short)(w.y & 0xffff); wf[3] = (float)(short)(w.y >> 16);
    wf[4] = (float)(short)(w.z & 0xffff); wf[5] = (float)(short)(w.z >> 16);
    wf[6] = (float)(short)(w.w & 0xffff); wf[7] = (float)(short)(w.w >> 16);
}

// ---------------------------------------------------------------------------
// Pass 1: gather 8 guidance values at neighbor positions, abs-sum normalize,
// quantize to int16 (x32767). Two adjacent voxels per thread -> one 256-bit
// sticky store. (Already runs at ~8.5 TB/s effective; unchanged.)
// ---------------------------------------------------------------------------
template <int DIR>
__global__ __launch_bounds__(256) void make_weights(
    const float* __restrict__ G, uint4* __restrict__ W)
{
    const int t = (blockIdx.x * 256 + threadIdx.x) * 2;
    const int z0 = t & 31, y = (t >> 5) & 255, x = t >> 13;

    uint4 wp[2];
#pragma unroll
    for (int v = 0; v < 2; ++v) {
        const int z = z0 + v;
        float g[8];
        float asum = 0.f;
#pragma unroll
        for (int k = 0; k < 8; ++k) {
            const int dr = c_dr[k], dc = c_dc[k];
            int nx, ny, nz; bool ok;
            if (DIR == 0)      { nx = x + dr; ny = y + dc; nz = z;
                                 ok = ((unsigned)nx < DX) & ((unsigned)ny < DY); }
            else if (DIR == 1) { nx = x + dr; ny = y;      nz = z + dc;
                                 ok = ((unsigned)nx < DX) & ((unsigned)nz < DZ); }
            else               { nx = x;      ny = y + dr; nz = z + dc;
                                 ok = ((unsigned)ny < DY) & ((unsigned)nz < DZ); }
            float gv = 0.f;
            if (ok) gv = ldcs(&G[(DIR * 8 + k) * VOL + (nx * DY + ny) * DZ + nz]);
            g[k] = gv;
            asum += fabsf(gv);
        }

        const float s = 32767.f / asum;
        int q[8];
#pragma unroll
        for (int k = 0; k < 8; ++k) q[k] = __float2int_rn(g[k] * s);

        wp[v].x = (q[0] & 0xffff) | (q[1] << 16);
        wp[v].y = (q[2] & 0xffff) | (q[3] << 16);
        wp[v].z = (q[4] & 0xffff) | (q[5] << 16);
        wp[v].w = (q[6] & 0xffff) | (q[7] << 16);
    }
    stg256_sticky(&W[t], wp[0], wp[1]);
}

// ---------------------------------------------------------------------------
// Pass 2 (x9): FOUR voxels (one aligned z-quad) per thread.
//   2 x LDG.256 weights, 1 float4 center, DIR0: 8 aligned float4 neighbors,
//   DIR1/2: 3 row float4 + 6 edge scalars, 1 float4 store.
// out = bc + (sum_k w_k*b_k - (sum_k w_k)*bc) / 32767.
// Invalid neighbors have w_k == 0; addresses are clamped (value unused).
// ---------------------------------------------------------------------------
template <int DIR>
__global__ __launch_bounds__(256) void prop_step(
    const uint4* __restrict__ W,
    const float* __restrict__ S,
    float* __restrict__ D)
{
    const int t  = (blockIdx.x * 256 + threadIdx.x) * 4;
    const int z0 = t & 31, y = (t >> 5) & 255, x = t >> 13;

    uint4 wq[4];
    ldg256_sticky(&W[t],     wq[0], wq[1]);
    ldg256_sticky(&W[t + 2], wq[2], wq[3]);
    const float4 bc = *reinterpret_cast<const float4*>(S + t);

    float b[8][4];   // neighbor value per k per voxel

    if (DIR == 0) {
        // Shifts in (x,y) only: every neighbor quad is an aligned float4.
#pragma unroll
        for (int k = 0; k < 8; ++k) {
            const int dr = c_dr[k], dc = c_dc[k];
            const bool ok = ((unsigned)(x + dr) < DX) & ((unsigned)(y + dc) < DY);
            const int delta = dr * (DY * DZ) + dc * DZ;
            const float4 q = *reinterpret_cast<const float4*>(S + (ok ? t + delta : t));
            b[k][0] = q.x; b[k][1] = q.y; b[k][2] = q.z; b[k][3] = q.w;
        }
    } else {
        // Row r in {-1,0,+1} along x (DIR1) or y (DIR2); col shift along z.
        // Per row: aligned quad + two edge scalars; build shifted quads in regs.
        float4 q[3]; float em[3], ep[3];
#pragma unroll
        for (int r = 0; r < 3; ++r) {
            const int d   = r - 1;
            const int row = (DIR == 1) ? d * (DY * DZ) : d * DZ;
            const bool rok = (DIR == 1) ? ((unsigned)(x + d) < DX)
                                        : ((unsigned)(y + d) < DY);
            const float* base = S + (rok ? t + row : t);
            q[r]  = *reinterpret_cast<const float4*>(base);
            em[r] = __ldg(base - (z0 > 0  ? 1 : 0));   // z0-1 (clamped at z0==0)
            ep[r] = __ldg(base + (z0 < 28 ? 4 : 0));   // z0+4 (clamped at z0==28)
        }
#pragma unroll
        for (int k = 0; k < 8; ++k) {
            const int r = c_dr[k] + 1, dc = c_dc[k];
            if (dc == 0) {
                b[k][0] = q[r].x; b[k][1] = q[r].y; b[k][2] = q[r].z; b[k][3] = q[r].w;
            } else if (dc == 1) {
                b[k][0] = q[r].y; b[k][1] = q[r].z; b[k][2] = q[r].w; b[k][3] = ep[r];
            } else {
                b[k][0] = em[r];  b[k][1] = q[r].x; b[k][2] = q[r].y; b[k][3] = q[r].z;
            }
        }
    }

    float res[4];
    const float bcv[4] = { bc.x, bc.y, bc.z, bc.w };
#pragma unroll
    for (int v = 0; v < 4; ++v) {
        float wf[8];
        decode8(wq[v], wf);
        float acc = 0.f, gs = 0.f;
#pragma unroll
        for (int k = 0; k < 8; ++k) {
            acc = fmaf(wf[k], b[k][v], acc);
            gs += wf[k];
        }
        res[v] = fmaf(fmaf(-gs, bcv[v], acc), 1.f / 32767.f, bcv[v]);
    }
    *reinterpret_cast<float4*>(D + t) = make_float4(res[0], res[1], res[2], res[3]);
}

extern "C" void kernel_launch(void* const* d_in, const int* in_sizes, int n_in,
                              void* d_out, int out_size)
{
    const float* G    = (const float*)d_in[0];  // guidance [24,256,256,32]
    const float* blur = (const float*)d_in[1];  // blur [1,256,256,32]
    float* out = (float*)d_out;

    void* wp = nullptr;  cudaGetSymbolAddress(&wp, g_weights);
    void* sp = nullptr;  cudaGetSymbolAddress(&sp, g_scratch);
    uint4* W   = (uint4*)wp;
    float* scr = (float*)sp;

    const int gridMW = (VOL / 2) / 256;   // 4096 blocks, 2 voxels/thread
    const int gridPS = (VOL / 4) / 256;   // 2048 blocks, 4 voxels/thread

    // Pass 1: build weights for the 3 directions (guidance read exactly once).
    make_weights<0><<<gridMW, 256>>>(G, W + 0 * VOL);
    make_weights<1><<<gridMW, 256>>>(G, W + 1 * VOL);
    make_weights<2><<<gridMW, 256>>>(G, W + 2 * VOL);

    // Pass 2: 9 propagation steps (dir 0,1,2 x 3), ping-pong so the 9th
    // write lands in d_out: targets out,scr,out,scr,out,scr,out,scr,out.
    const float* src = blur;
    float* bufs[2] = { out, scr };
    int wsel = 0;

    for (int it = 0; it < 3; ++it) {
        prop_step<0><<<gridPS, 256>>>(W + 0 * VOL, src, bufs[wsel]);
        src = bufs[wsel]; wsel ^= 1;
        prop_step<1><<<gridPS, 256>>>(W + 1 * VOL, src, bufs[wsel]);
        src = bufs[wsel]; wsel ^= 1;
        prop_step<2><<<gridPS, 256>>>(W + 2 * VOL, src, bufs[wsel]);
        src = bufs[wsel]; wsel ^= 1;
    }
}